// round 1
// baseline (speedup 1.0000x reference)
#include <cuda_runtime.h>
#include <cuda_bf16.h>

// Problem constants
// B=2, S=2048, D=1024, H=8, HKV=2, HD=128, G=4
#define SCALE_ATT 0.08838834764831845f

// ---------------- device scratch (no allocations allowed) ----------------
__device__ float g_WqEff[1024 * 1024];   // folded q_weight (q_mat absorbed)
__device__ float g_WkEff[256 * 1024];    // folded k_weight (k_mat absorbed)
__device__ float g_bqEff[1024];
__device__ float g_bkEff[256];
__device__ float g_Q[2 * 8 * 2048 * 128];   // (B,H,S,HD)
__device__ float g_K[2 * 2 * 2048 * 128];   // (B,HKV,S,HD)
__device__ float g_V[2 * 2 * 2048 * 128];   // (B,HKV,S,HD)
__device__ float g_O[2 * 2048 * 8 * 128];   // (B,S,H,HD) -> rows for final GEMM

// ---------------- weight folding: Weff[h*128+j, d] = sum_i mat[i,j] * W[h*128+i, d]
template <int WHICH>
__global__ void fold_w_k(const float* __restrict__ W, const float* __restrict__ mat) {
    int o = blockIdx.x;            // output row (h*128 + j)
    int h = o >> 7, j = o & 127;
    int d = blockIdx.y * 256 + threadIdx.x;
    const float* wrow = W + (h * 128) * 1024 + d;
    float acc = 0.f;
#pragma unroll 8
    for (int i = 0; i < 128; i++) acc += mat[i * 128 + j] * wrow[i * 1024];
    if (WHICH == 0) g_WqEff[o * 1024 + d] = acc;
    else            g_WkEff[o * 1024 + d] = acc;
}

template <int WHICH>
__global__ void fold_b_k(const float* __restrict__ bias, const float* __restrict__ mat) {
    const int HOUT = (WHICH == 0) ? 1024 : 256;
    int o = blockIdx.x * blockDim.x + threadIdx.x;
    if (o >= HOUT) return;
    int h = o >> 7, j = o & 127;
    float acc = 0.f;
    for (int i = 0; i < 128; i++) acc += bias[h * 128 + i] * mat[i * 128 + j];
    if (WHICH == 0) g_bqEff[o] = acc;
    else            g_bkEff[o] = acc;
}

// ---------------- SGEMM: C[M,N] = A[M,1024] @ W[N,1024]^T (+bias, scatter epilogue)
// BM=128, BN=64, BK=16, 256 threads, 8x4 microtile.
// MODE 0: A = hidden_states, N=1536 (Q|K|V regions), scatter into g_Q/g_K/g_V (+bias)
// MODE 1: A = g_O, W = o_weight, N=1024, plain store to out
template <int MODE>
__global__ void __launch_bounds__(256) sgemm_k(const float* __restrict__ A_,
                                               const float* __restrict__ Wext,
                                               const float* __restrict__ bv,
                                               float* __restrict__ out) {
    __shared__ float As[16][132];  // [k][m], padded
    __shared__ float Bs[16][68];   // [k][n], padded

    const float* Ap = (MODE == 0) ? A_ : (const float*)g_O;
    int n0 = blockIdx.x * 64;
    int m0 = blockIdx.y * 128;

    const float* Bmat;
    int nb;
    if (MODE == 0) {
        if (n0 < 1024)      { Bmat = g_WqEff; nb = n0; }
        else if (n0 < 1280) { Bmat = g_WkEff; nb = n0 - 1024; }
        else                { Bmat = Wext;    nb = n0 - 1280; }   // v_weight
    } else {
        Bmat = Wext; nb = n0;
    }

    int tid = threadIdx.x;
    int tr = tid >> 4;   // 0..15 -> 8 rows each
    int tc = tid & 15;   // 0..15 -> 4 cols each

    float acc[8][4];
#pragma unroll
    for (int i = 0; i < 8; i++)
#pragma unroll
        for (int j = 0; j < 4; j++) acc[i][j] = 0.f;

    for (int k0 = 0; k0 < 1024; k0 += 16) {
#pragma unroll
        for (int l = 0; l < 8; l++) {
            int flat = l * 256 + tid;
            int mm = flat >> 4, kk = flat & 15;
            As[kk][mm] = Ap[(m0 + mm) * 1024 + k0 + kk];
        }
#pragma unroll
        for (int l = 0; l < 4; l++) {
            int flat = l * 256 + tid;
            int mm = flat >> 4, kk = flat & 15;
            Bs[kk][mm] = Bmat[(nb + mm) * 1024 + k0 + kk];
        }
        __syncthreads();
#pragma unroll
        for (int kk = 0; kk < 16; kk++) {
            float4 t0 = *(const float4*)&As[kk][tr * 8];
            float4 t1 = *(const float4*)&As[kk][tr * 8 + 4];
            float4 t2 = *(const float4*)&Bs[kk][tc * 4];
            float a[8] = {t0.x, t0.y, t0.z, t0.w, t1.x, t1.y, t1.z, t1.w};
            float b[4] = {t2.x, t2.y, t2.z, t2.w};
#pragma unroll
            for (int i = 0; i < 8; i++)
#pragma unroll
                for (int j = 0; j < 4; j++) acc[i][j] += a[i] * b[j];
        }
        __syncthreads();
    }

    if (MODE == 0) {
#pragma unroll
        for (int i = 0; i < 8; i++) {
            int m = m0 + tr * 8 + i;
            int bb = m >> 11, s = m & 2047;
#pragma unroll
            for (int j = 0; j < 4; j++) {
                int n = n0 + tc * 4 + j;
                float v = acc[i][j];
                if (n < 1024) {
                    int h = n >> 7, hd = n & 127;
                    g_Q[(((bb * 8 + h) * 2048) + s) * 128 + hd] = v + g_bqEff[n];
                } else if (n < 1280) {
                    int nn = n - 1024;
                    int h = nn >> 7, hd = nn & 127;
                    g_K[(((bb * 2 + h) * 2048) + s) * 128 + hd] = v + g_bkEff[nn];
                } else {
                    int nn = n - 1280;
                    int h = nn >> 7, hd = nn & 127;
                    g_V[(((bb * 2 + h) * 2048) + s) * 128 + hd] = v + bv[nn];
                }
            }
        }
    } else {
#pragma unroll
        for (int i = 0; i < 8; i++) {
            int m = m0 + tr * 8 + i;
            float4 st = make_float4(acc[i][0], acc[i][1], acc[i][2], acc[i][3]);
            *(float4*)&out[m * 1024 + n0 + tc * 4] = st;
        }
    }
}

// ---------------- RoPE (in-place), cos/sin broadcast over heads
template <int WHICH>
__global__ void rope_k(const float* __restrict__ cosb, const float* __restrict__ sinb) {
    const int NH = (WHICH == 0) ? 8 : 2;
    float* buf = (WHICH == 0) ? g_Q : g_K;
    int idx = blockIdx.x * 256 + threadIdx.x;
    int total = 2 * NH * 2048 * 64;
    if (idx >= total) return;
    int j = idx & 63;
    int t = idx >> 6;
    int s = t & 2047; t >>= 11;
    int h = t % NH;
    int b = t / NH;
    float* p = buf + (((b * NH + h) * 2048) + s) * 128;
    const float* cp = cosb + (b * 2048 + s) * 128;
    const float* sp = sinb + (b * 2048 + s) * 128;
    float x1 = p[j], x2 = p[j + 64];
    p[j]      = x1 * cp[j]      - x2 * sp[j];
    p[j + 64] = x2 * cp[j + 64] + x1 * sp[j + 64];
}

// ---------------- causal flash attention, fp32 SIMT
// Q tile 64 rows, KV tile 32 keys, 128 threads: thread (tr=tid/8, tc=tid%8)
// S-frag 4x4 (rows tr*4.., cols tc*4..); O-frag 4 rows x 16 cols (cols tc*4+32g)
__global__ void __launch_bounds__(128) attn_k() {
    extern __shared__ float sm[];
    float* QsT = sm;                    // [128][68]  (d-major, padded)
    float* KsT = sm + 128 * 68;         // [128][36]
    float* Vs  = KsT + 128 * 36;        // [32][128]  (natural)
    float* Ps  = Vs + 32 * 128;         // [64][36]

    int q0 = blockIdx.x * 64;
    int h = blockIdx.y, b = blockIdx.z;
    int kv = h >> 2;  // G = 4
    const float* Qg = g_Q + (((b * 8 + h) * 2048) + q0) * 128;
    const float* Kg = g_K + ((b * 2 + kv) * 2048) * 128;
    const float* Vg = g_V + ((b * 2 + kv) * 2048) * 128;

    int tid = threadIdx.x;
    int tr = tid >> 3, tc = tid & 7;

    // load Q transposed: QsT[d][r]
    for (int r = 0; r < 64; r++) QsT[tid * 68 + r] = Qg[r * 128 + tid];
    __syncthreads();

    float Of[4][16];
#pragma unroll
    for (int i = 0; i < 4; i++)
#pragma unroll
        for (int c = 0; c < 16; c++) Of[i][c] = 0.f;
    float mrow[4] = {-3e38f, -3e38f, -3e38f, -3e38f};
    float lrow[4] = {0.f, 0.f, 0.f, 0.f};

    int nkt = (q0 >> 5) + 2;  // key tiles up to causal limit
    for (int kt = 0; kt < nkt; kt++) {
        int kbase = kt * 32;
        // load K transposed + V natural
        for (int c = 0; c < 32; c++) KsT[tid * 36 + c] = Kg[(kbase + c) * 128 + tid];
#pragma unroll
        for (int l = 0; l < 8; l++) {
            int idx4 = l * 128 + tid;
            ((float4*)Vs)[idx4] = ((const float4*)(Vg + kbase * 128))[idx4];
        }
        __syncthreads();

        // S = Q K^T (4x4 frag)
        float sf[4][4];
#pragma unroll
        for (int i = 0; i < 4; i++)
#pragma unroll
            for (int j = 0; j < 4; j++) sf[i][j] = 0.f;
#pragma unroll 8
        for (int d = 0; d < 128; d++) {
            float4 tq = *(const float4*)&QsT[d * 68 + tr * 4];
            float4 tk = *(const float4*)&KsT[d * 36 + tc * 4];
            float qa[4] = {tq.x, tq.y, tq.z, tq.w};
            float kb[4] = {tk.x, tk.y, tk.z, tk.w};
#pragma unroll
            for (int i = 0; i < 4; i++)
#pragma unroll
                for (int j = 0; j < 4; j++) sf[i][j] += qa[i] * kb[j];
        }

        // online softmax
#pragma unroll
        for (int i = 0; i < 4; i++) {
            int qg = q0 + tr * 4 + i;
            float mx = -3e38f;
#pragma unroll
            for (int j = 0; j < 4; j++) {
                int kc = kbase + tc * 4 + j;
                float v = (kc <= qg) ? sf[i][j] * SCALE_ATT : -1e30f;
                sf[i][j] = v;
                mx = fmaxf(mx, v);
            }
            mx = fmaxf(mx, __shfl_xor_sync(0xffffffffu, mx, 1));
            mx = fmaxf(mx, __shfl_xor_sync(0xffffffffu, mx, 2));
            mx = fmaxf(mx, __shfl_xor_sync(0xffffffffu, mx, 4));
            float newm = fmaxf(mrow[i], mx);
            float corr = __expf(mrow[i] - newm);
            mrow[i] = newm;
            float ls = 0.f;
#pragma unroll
            for (int j = 0; j < 4; j++) {
                float p = __expf(sf[i][j] - newm);
                sf[i][j] = p;
                ls += p;
            }
            ls += __shfl_xor_sync(0xffffffffu, ls, 1);
            ls += __shfl_xor_sync(0xffffffffu, ls, 2);
            ls += __shfl_xor_sync(0xffffffffu, ls, 4);
            lrow[i] = lrow[i] * corr + ls;
#pragma unroll
            for (int c = 0; c < 16; c++) Of[i][c] *= corr;
            *(float4*)&Ps[(tr * 4 + i) * 36 + tc * 4] =
                make_float4(sf[i][0], sf[i][1], sf[i][2], sf[i][3]);
        }
        __syncthreads();

        // O += P @ V
#pragma unroll 4
        for (int k = 0; k < 32; k++) {
            float pr[4];
#pragma unroll
            for (int i = 0; i < 4; i++) pr[i] = Ps[(tr * 4 + i) * 36 + k];
#pragma unroll
            for (int g = 0; g < 4; g++) {
                float4 vv = *(const float4*)&Vs[k * 128 + tc * 4 + g * 32];
                float vx[4] = {vv.x, vv.y, vv.z, vv.w};
#pragma unroll
                for (int i = 0; i < 4; i++)
#pragma unroll
                    for (int u = 0; u < 4; u++) Of[i][g * 4 + u] += pr[i] * vx[u];
            }
        }
        __syncthreads();
    }

    // epilogue: normalize and store to (B,S,H,HD)
#pragma unroll
    for (int i = 0; i < 4; i++) {
        float inv = 1.f / lrow[i];
        int qrow = q0 + tr * 4 + i;
        float* op = g_O + (((b * 2048 + qrow) * 8) + h) * 128;
#pragma unroll
        for (int g = 0; g < 4; g++) {
            float4 st = make_float4(Of[i][g * 4 + 0] * inv, Of[i][g * 4 + 1] * inv,
                                    Of[i][g * 4 + 2] * inv, Of[i][g * 4 + 3] * inv);
            *(float4*)&op[tc * 4 + g * 32] = st;
        }
    }
}

// ---------------- launch ----------------
extern "C" void kernel_launch(void* const* d_in, const int* in_sizes, int n_in,
                              void* d_out, int out_size) {
    const float* hs   = (const float*)d_in[0];
    const float* cosb = (const float*)d_in[1];
    const float* sinb = (const float*)d_in[2];
    // d_in[3] attention_mask: exactly causal -> implemented analytically
    const float* qw   = (const float*)d_in[4];
    const float* kw   = (const float*)d_in[5];
    const float* vw   = (const float*)d_in[6];
    const float* ow   = (const float*)d_in[7];
    const float* qb   = (const float*)d_in[8];
    const float* kb   = (const float*)d_in[9];
    const float* vb   = (const float*)d_in[10];
    const float* qmat = (const float*)d_in[11];
    const float* kmat = (const float*)d_in[12];
    // d_in[13], d_in[14]: tau_kv / tau_group — permutation + inverse cancel exactly
    float* out = (float*)d_out;

    const int ATTN_SMEM = (128 * 68 + 128 * 36 + 32 * 128 + 64 * 36) * 4;  // 78848 B
    cudaFuncSetAttribute(attn_k, cudaFuncAttributeMaxDynamicSharedMemorySize, ATTN_SMEM);

    // 1) fold q_mat / k_mat into projection weights + biases
    fold_w_k<0><<<dim3(1024, 4), 256>>>(qw, qmat);
    fold_w_k<1><<<dim3(256, 4), 256>>>(kw, kmat);
    fold_b_k<0><<<4, 256>>>(qb, qmat);
    fold_b_k<1><<<1, 256>>>(kb, kmat);

    // 2) fused QKV projection (M=4096, N=1536) with scatter epilogue
    sgemm_k<0><<<dim3(24, 32), 256>>>(hs, vw, vb, nullptr);

    // 3) RoPE in-place on Q and K
    rope_k<0><<<8192, 256>>>(cosb, sinb);
    rope_k<1><<<2048, 256>>>(cosb, sinb);

    // 4) causal flash attention (GQA, G=4)
    attn_k<<<dim3(32, 8, 2), 128, ATTN_SMEM>>>();

    // 5) output projection (M=4096, N=1024)
    sgemm_k<1><<<dim3(16, 32), 256>>>(nullptr, ow, nullptr, out);
}